// round 15
// baseline (speedup 1.0000x reference)
#include <cuda_runtime.h>
#include <cuda_fp16.h>
#include <math.h>

#define B 64
#define N 1024
#define F_IN 64
#define E 128
#define TOPK 32
#define NEG_SLOPE 0.2f

// ---------------- scratch (device globals; no allocation allowed) ----------
__device__ __align__(16) __half g_h[B * N * E];    // 16 MB, fp16 storage
__device__ float g_es[B * N];
__device__ float g_ed[B * N];
__device__ __align__(16) float g_embn[N * E];      // normalized emb
__device__ float g_eemb_s[N];
__device__ float g_eemb_d[N];
__device__ __align__(16) float g_ws[2 * F_IN];     // [ws_src | ws_dst]
__device__ int   g_idx[N * TOPK];
__device__ __align__(16) float g_sims[N * N];      // 4 MB cosine sims
__device__ float g_part[2 * B * N];                // per-e-half partial dots
#define WT_STRIDE 72
__device__ __align__(16) __half g_wt[E * WT_STRIDE];  // W^T fp16, padded rows

// ---------------- K_pre: fused ws + W^T + emb-normalize --------------------
__global__ void k_pre(const float* __restrict__ emb,
                      const float* __restrict__ Wfe,
                      const float* __restrict__ a_src,
                      const float* __restrict__ a_dst) {
    int bid = blockIdx.x;
    int t = threadIdx.x;  // 128

    if (bid < N) {
        int n = bid;
        int lane = t & 31, wid = t >> 5;
        __shared__ float sm[12];
        float v  = emb[n * E + t];
        float r0 = v * v;
        float r1 = v * a_src[E + t];
        float r2 = v * a_dst[E + t];
        #pragma unroll
        for (int o = 16; o; o >>= 1) {
            r0 += __shfl_xor_sync(0xffffffffu, r0, o);
            r1 += __shfl_xor_sync(0xffffffffu, r1, o);
            r2 += __shfl_xor_sync(0xffffffffu, r2, o);
        }
        if (lane == 0) { sm[wid] = r0; sm[4 + wid] = r1; sm[8 + wid] = r2; }
        __syncthreads();
        float sumsq = sm[0] + sm[1] + sm[2] + sm[3];
        g_embn[n * E + t] = v * rsqrtf(sumsq);
        if (t == 0) {
            g_eemb_s[n] = sm[4] + sm[5] + sm[6] + sm[7];
            g_eemb_d[n] = sm[8] + sm[9] + sm[10] + sm[11];
        }
    } else if (bid == N) {
        if (t < F_IN) {
            float s = 0.f;
            #pragma unroll 8
            for (int e = 0; e < E; e++) s += Wfe[t * E + e] * a_src[e];
            g_ws[t] = s;
        } else {
            int f = t - F_IN;
            float s = 0.f;
            #pragma unroll 8
            for (int e = 0; e < E; e++) s += Wfe[f * E + e] * a_dst[e];
            g_ws[F_IN + f] = s;
        }
    } else {
        int idx = (bid - N - 1) * 128 + t;   // 0..8191 = e*64+f
        int e = idx >> 6, f = idx & 63;
        g_wt[e * WT_STRIDE + f] = __float2half_rn(Wfe[f * E + e]);
    }
}

// ---------------- K1b-sim: tiled GEMM, k-major smem (float4 loads) ---------
#define KC 32
__global__ void __launch_bounds__(256) k1b_sim() {
    __shared__ float As[KC][68];
    __shared__ float Bs[KC][68];
    int tid = threadIdx.x;
    int r0 = blockIdx.y * 64;
    int c0 = blockIdx.x * 64;
    int lrow = tid >> 5, lcol = tid & 31;
    int ty = tid >> 4, tx = tid & 15;

    float acc[4][4];
    #pragma unroll
    for (int i = 0; i < 4; i++)
        #pragma unroll
        for (int j = 0; j < 4; j++) acc[i][j] = 0.f;

    for (int kk = 0; kk < E; kk += KC) {
        #pragma unroll
        for (int it = 0; it < 8; it++) {
            int row = lrow + it * 8;
            As[lcol][row] = g_embn[(size_t)(r0 + row) * E + kk + lcol];
            Bs[lcol][row] = g_embn[(size_t)(c0 + row) * E + kk + lcol];
        }
        __syncthreads();

        #pragma unroll
        for (int k = 0; k < KC; k++) {
            float4 av = *(const float4*)&As[k][ty * 4];
            float4 bv = *(const float4*)&Bs[k][tx * 4];
            float a[4] = {av.x, av.y, av.z, av.w};
            float b[4] = {bv.x, bv.y, bv.z, bv.w};
            #pragma unroll
            for (int i = 0; i < 4; i++)
                #pragma unroll
                for (int j = 0; j < 4; j++) acc[i][j] += a[i] * b[j];
        }
        __syncthreads();
    }

    #pragma unroll
    for (int i = 0; i < 4; i++) {
        #pragma unroll
        for (int j = 0; j < 4; j++)
            g_sims[(size_t)(r0 + ty * 4 + i) * N + c0 + tx * 4 + j] = acc[i][j];
    }
}

// ---------------- K1b-sel: warp per row, top-32 via REDUX ------------------
__device__ __forceinline__ unsigned f2ord(float f) {
    unsigned b = __float_as_uint(f);
    return ((int)b < 0) ? ~b : (b | 0x80000000u);
}

__global__ void __launch_bounds__(256) k1b_sel() {
    int tid = threadIdx.x;
    int wid = tid >> 5, lane = tid & 31;
    int r = blockIdx.x * 8 + wid;

    const float* srow = g_sims + (size_t)r * N;
    float vals[32];
    #pragma unroll
    for (int j = 0; j < 32; j++) vals[j] = srow[j * 32 + lane];

    float bv = vals[0]; int bj = 0;
    #pragma unroll
    for (int j = 1; j < 32; j++)
        if (vals[j] > bv) { bv = vals[j]; bj = j; }

    for (int round = 0; round < TOPK; round++) {
        unsigned u  = f2ord(bv);
        unsigned mu = __reduce_max_sync(0xffffffffu, u);
        unsigned cand = (u == mu) ? (unsigned)(bj * 32 + lane) : 0x7FFFFFFFu;
        int wi = (int)__reduce_min_sync(0xffffffffu, cand);
        if (lane == 0) g_idx[r * TOPK + round] = wi;
        if (((wi & 31) == lane) && ((wi >> 5) == bj)) {
            #pragma unroll
            for (int j = 0; j < 32; j++) if (j == bj) vals[j] = -INFINITY;
            bv = vals[0]; bj = 0;
            #pragma unroll
            for (int j = 1; j < 32; j++)
                if (vals[j] > bv) { bv = vals[j]; bj = j; }
        }
        __syncwarp();
    }
}

// ---------------- K2: h = x @ W_fe via tensor cores; fused e_s/e_d ---------
// 512 thr = 16 warps (8 m x 2 n); tile 128 tokens x 128 E; K = 64.
#define TOK 128
#define XS_STRIDE 72
#define CS_STRIDE 136

__device__ __forceinline__ void mma16816(float* c, const unsigned* a, const unsigned* b) {
    asm volatile(
        "mma.sync.aligned.m16n8k16.row.col.f32.f16.f16.f32 "
        "{%0,%1,%2,%3}, {%4,%5,%6,%7}, {%8,%9}, {%0,%1,%2,%3};\n"
        : "+f"(c[0]), "+f"(c[1]), "+f"(c[2]), "+f"(c[3])
        : "r"(a[0]), "r"(a[1]), "r"(a[2]), "r"(a[3]), "r"(b[0]), "r"(b[1]));
}

__global__ void __launch_bounds__(512) k2_tc(const float* __restrict__ x) {
    __shared__ __align__(16) char sbuf[TOK * XS_STRIDE * 2 + E * WT_STRIDE * 2];
    __half* xs = (__half*)sbuf;
    __half* Ws = (__half*)(sbuf + TOK * XS_STRIDE * 2);
    int tid = threadIdx.x;
    int t0 = blockIdx.x * TOK;

    {
        const uint4* wsrc = (const uint4*)g_wt;
        uint4* wdst = (uint4*)Ws;
        #pragma unroll
        for (int i = 0; i < 3; i++) {
            int idx = tid + i * 512;
            if (idx < (E * WT_STRIDE * 2) / 16) wdst[idx] = wsrc[idx];
        }
        const float4* xsrc = (const float4*)(x + (size_t)t0 * F_IN);
        const float4* ws4  = (const float4*)g_ws;
        int c4 = tid & 15;
        float4 wsv = __ldg(ws4 + c4);
        float4 wdv = __ldg(ws4 + 16 + c4);
        #pragma unroll
        for (int it = 0; it < 4; it++) {
            int idx = tid + it * 512;     // 0..2047 float4
            int row = idx >> 4;
            float4 v = xsrc[idx];
            __half2* dst = (__half2*)(xs + row * XS_STRIDE + c4 * 4);
            dst[0] = __floats2half2_rn(v.x, v.y);
            dst[1] = __floats2half2_rn(v.z, v.w);
            float s = v.x * wsv.x + v.y * wsv.y + v.z * wsv.z + v.w * wsv.w;
            float d = v.x * wdv.x + v.y * wdv.y + v.z * wdv.z + v.w * wdv.w;
            #pragma unroll
            for (int o = 8; o; o >>= 1) {
                s += __shfl_xor_sync(0xffffffffu, s, o);
                d += __shfl_xor_sync(0xffffffffu, d, o);
            }
            if (c4 == 0) {
                int gt = t0 + row;
                int n = gt & (N - 1);
                g_es[gt] = s + __ldg(&g_eemb_s[n]);
                g_ed[gt] = d + __ldg(&g_eemb_d[n]);
            }
        }
    }
    __syncthreads();

    int lane = tid & 31, warp = tid >> 5;
    int wm = warp & 7, wn = warp >> 3;
    int gid = lane >> 2, qid = lane & 3;

    float c[8][4];
    #pragma unroll
    for (int ni = 0; ni < 8; ni++)
        #pragma unroll
        for (int q = 0; q < 4; q++) c[ni][q] = 0.f;

    #pragma unroll
    for (int kk = 0; kk < F_IN; kk += 16) {
        unsigned a[4];
        {
            int r = wm * 16 + gid;
            int cb = qid * 2 + kk;
            a[0] = *(unsigned*)(xs + r * XS_STRIDE + cb);
            a[1] = *(unsigned*)(xs + (r + 8) * XS_STRIDE + cb);
            a[2] = *(unsigned*)(xs + r * XS_STRIDE + cb + 8);
            a[3] = *(unsigned*)(xs + (r + 8) * XS_STRIDE + cb + 8);
        }
        #pragma unroll
        for (int ni = 0; ni < 8; ni++) {
            int col = wn * 64 + ni * 8 + gid;
            int rb = qid * 2 + kk;
            unsigned bb[2];
            bb[0] = *(unsigned*)(Ws + col * WT_STRIDE + rb);
            bb[1] = *(unsigned*)(Ws + col * WT_STRIDE + rb + 8);
            mma16816(c[ni], a, bb);
        }
    }
    __syncthreads();

    __half* cs = (__half*)sbuf;
    #pragma unroll
    for (int ni = 0; ni < 8; ni++) {
        int r = wm * 16 + gid;
        int e = wn * 64 + ni * 8 + qid * 2;
        *(__half2*)(cs + r * CS_STRIDE + e) =
            __floats2half2_rn(c[ni][0], c[ni][1]);
        *(__half2*)(cs + (r + 8) * CS_STRIDE + e) =
            __floats2half2_rn(c[ni][2], c[ni][3]);
    }
    __syncthreads();

    uint4* dst = (uint4*)(g_h + (size_t)t0 * E);
    #pragma unroll
    for (int it = 0; it < 4; it++) {
        int idx = tid + it * 512;
        int row = idx >> 4;
        int c8  = idx & 15;
        dst[idx] = *(uint4*)(cs + row * CS_STRIDE + c8 * 8);
    }
}

// ---------------- K3: smem-resident SpMM attention ------------------------
__global__ void __launch_bounds__(1024) k3_spmm(const float* __restrict__ lin_W) {
    extern __shared__ __half hs[];     // [1024 rows][64 halves] = 128 KB
    int bx = blockIdx.x;
    int b  = bx >> 1;
    int h0 = (bx & 1) << 6;
    int tid = threadIdx.x;

    {
        const uint4* src = (const uint4*)(g_h + (((size_t)b) << 10) * E);
        uint4* dst = (uint4*)hs;
        int cbase = h0 >> 3;
        #pragma unroll
        for (int i = 0; i < 8; i++) {
            int idx = tid + (i << 10);
            int n = idx >> 3, c = idx & 7;
            dst[idx] = src[(n << 4) + cbase + c];
        }
    }
    __syncthreads();

    int lane = tid & 31, wid = tid >> 5;
    int g = lane >> 3, l8 = lane & 7;

    float lw[8];
    {
        const float4* lw4 = (const float4*)lin_W;
        float4 a0 = lw4[(h0 >> 2) + l8 * 2];
        float4 a1 = lw4[(h0 >> 2) + l8 * 2 + 1];
        lw[0] = a0.x; lw[1] = a0.y; lw[2] = a0.z; lw[3] = a0.w;
        lw[4] = a1.x; lw[5] = a1.y; lw[6] = a1.z; lw[7] = a1.w;
    }

    for (int pass = 0; pass < 8; pass++) {
        int n = (wid << 5) + (pass << 2) + g;
        int t = (b << 10) + n;

        float sc[4]; int ii[4];
        float es = g_es[t];
        float m = -1e30f;
        #pragma unroll
        for (int j = 0; j < 4; j++) {
            int k = l8 + (j << 3);
            int i = g_idx[(n << 5) + k];
            float v = es + g_ed[(b << 10) + i];
            v = v >= 0.f ? v : NEG_SLOPE * v;
            sc[j] = v; ii[j] = i;
            m = fmaxf(m, v);
        }
        #pragma unroll
        for (int o = 4; o; o >>= 1) m = fmaxf(m, __shfl_xor_sync(0xffffffffu, m, o));

        float s = 0.f;
        unsigned pk[4];
        #pragma unroll
        for (int j = 0; j < 4; j++) {
            float pe = __expf(sc[j] - m);
            unsigned pt = __float_as_uint(pe) & 0xFFFFFC00u;
            s += __uint_as_float(pt);
            pk[j] = pt | (unsigned)ii[j];
        }
        #pragma unroll
        for (int o = 4; o; o >>= 1) s += __shfl_xor_sync(0xffffffffu, s, o);

        float acc[8];
        #pragma unroll
        for (int q = 0; q < 8; q++) acc[q] = 0.f;
        #pragma unroll
        for (int k = 0; k < 32; k++) {
            unsigned w = __shfl_sync(0xffffffffu, pk[k >> 3], (lane & 24) + (k & 7));
            int   ridx = (int)(w & 0x3FFu);
            float a    = __uint_as_float(w & 0xFFFFFC00u);
            uint4 hv = ((const uint4*)hs)[(ridx << 3) + l8];
            const __half2* hp = (const __half2*)&hv;
            #pragma unroll
            for (int q = 0; q < 4; q++) {
                float2 f = __half22float2(hp[q]);
                acc[q * 2]     += a * f.x;
                acc[q * 2 + 1] += a * f.y;
            }
        }
        float part = 0.f;
        #pragma unroll
        for (int q = 0; q < 8; q++) part += fmaxf(acc[q], 0.f) * lw[q];
        part *= (1.f / s);
        #pragma unroll
        for (int o = 4; o; o >>= 1) part += __shfl_xor_sync(0xffffffffu, part, o);
        if (l8 == 0) g_part[((bx & 1) << 16) + t] = part;
    }
}

// ---------------- K_comb: combine e-half partials + bias -------------------
__global__ void k_comb(const float* __restrict__ lin_b, float* __restrict__ y) {
    int t = blockIdx.x * 256 + threadIdx.x;
    y[t] = g_part[t] + g_part[(B * N) + t] + lin_b[0];
}

// ---------------- launch: fork emb path (sim+sel) vs x path (k2) -----------
extern "C" void kernel_launch(void* const* d_in, const int* in_sizes, int n_in,
                              void* d_out, int out_size) {
    const float* x     = (const float*)d_in[0];
    const float* emb   = (const float*)d_in[1];
    const float* Wfe   = (const float*)d_in[2];
    const float* a_src = (const float*)d_in[3];
    const float* a_dst = (const float*)d_in[4];
    const float* lin_W = (const float*)d_in[5];
    const float* lin_b = (const float*)d_in[6];
    float* y = (float*)d_out;

    static cudaStream_t s2 = nullptr;
    static cudaEvent_t evFork = nullptr, evJoin = nullptr;
    if (s2 == nullptr) {
        cudaStreamCreateWithFlags(&s2, cudaStreamNonBlocking);
        cudaEventCreateWithFlags(&evFork, cudaEventDisableTiming);
        cudaEventCreateWithFlags(&evJoin, cudaEventDisableTiming);
        cudaFuncSetAttribute(k3_spmm, cudaFuncAttributeMaxDynamicSharedMemorySize,
                             131072);
    }

    k_pre<<<N + 1 + 64, 128>>>(emb, Wfe, a_src, a_dst);
    cudaEventRecord(evFork, 0);
    cudaStreamWaitEvent(s2, evFork, 0);
    {   // emb path on side stream
        dim3 gsim(N / 64, N / 64);
        k1b_sim<<<gsim, 256, 0, s2>>>();
        k1b_sel<<<N / 8, 256, 0, s2>>>();
    }
    cudaEventRecord(evJoin, s2);
    k2_tc<<<(B * N) / TOK, 512>>>(x);              // x path on main stream
    cudaStreamWaitEvent(0, evJoin, 0);
    k3_spmm<<<2 * B, 1024, 131072>>>(lin_W);
    k_comb<<<(B * N) / 256, 256>>>(lin_b, y);
}

// round 16
// speedup vs baseline: 1.1282x; 1.1282x over previous
#include <cuda_runtime.h>
#include <cuda_fp16.h>
#include <math.h>

#define B 64
#define N 1024
#define F_IN 64
#define E 128
#define TOPK 32
#define NEG_SLOPE 0.2f

// ---------------- scratch (device globals; no allocation allowed) ----------
__device__ __align__(16) __half g_h[B * N * E];    // 16 MB, fp16 storage
__device__ float g_es[B * N];
__device__ float g_ed[B * N];
__device__ __align__(16) float g_embn[N * E];      // normalized emb
__device__ float g_eemb_s[N];
__device__ float g_eemb_d[N];
__device__ __align__(16) float g_ws[2 * F_IN];     // [ws_src | ws_dst]
__device__ int   g_idx[N * TOPK];
__device__ __align__(16) float g_sims[N * N];      // 4 MB cosine sims
#define WT_STRIDE 72
__device__ __align__(16) __half g_wt[E * WT_STRIDE];  // W^T fp16, padded rows

// ---------------- K_pre: fused ws + W^T + emb-normalize + y-zero -----------
__global__ void k_pre(const float* __restrict__ emb,
                      const float* __restrict__ Wfe,
                      const float* __restrict__ a_src,
                      const float* __restrict__ a_dst,
                      float* __restrict__ y) {
    int bid = blockIdx.x;
    int t = threadIdx.x;  // 128

    if (bid < N) {
        int n = bid;
        int lane = t & 31, wid = t >> 5;
        __shared__ float sm[12];
        float v  = emb[n * E + t];
        float r0 = v * v;
        float r1 = v * a_src[E + t];
        float r2 = v * a_dst[E + t];
        #pragma unroll
        for (int o = 16; o; o >>= 1) {
            r0 += __shfl_xor_sync(0xffffffffu, r0, o);
            r1 += __shfl_xor_sync(0xffffffffu, r1, o);
            r2 += __shfl_xor_sync(0xffffffffu, r2, o);
        }
        if (lane == 0) { sm[wid] = r0; sm[4 + wid] = r1; sm[8 + wid] = r2; }
        // zero this block's slice of y (64 tokens * 64 batches / 1024 blocks)
        if (t < 64) y[bid * 64 + t] = 0.f;
        __syncthreads();
        float sumsq = sm[0] + sm[1] + sm[2] + sm[3];
        g_embn[n * E + t] = v * rsqrtf(sumsq);
        if (t == 0) {
            g_eemb_s[n] = sm[4] + sm[5] + sm[6] + sm[7];
            g_eemb_d[n] = sm[8] + sm[9] + sm[10] + sm[11];
        }
    } else if (bid == N) {
        if (t < F_IN) {
            float s = 0.f;
            #pragma unroll 8
            for (int e = 0; e < E; e++) s += Wfe[t * E + e] * a_src[e];
            g_ws[t] = s;
        } else {
            int f = t - F_IN;
            float s = 0.f;
            #pragma unroll 8
            for (int e = 0; e < E; e++) s += Wfe[f * E + e] * a_dst[e];
            g_ws[F_IN + f] = s;
        }
    } else {
        int idx = (bid - N - 1) * 128 + t;   // 0..8191 = e*64+f
        int e = idx >> 6, f = idx & 63;
        g_wt[e * WT_STRIDE + f] = __float2half_rn(Wfe[f * E + e]);
    }
}

// ---------------- K1b-sim: symmetric tiled GEMM (upper triangle only) ------
// 136 blocks = (bi<=bj) 64x64 tiles; off-diagonal tiles written twice
// (direct + smem-transposed mirror). Values bit-identical to full GEMM.
#define KC 32
__global__ void __launch_bounds__(256) k1b_sim() {
    __shared__ float sbuf[2 * KC * 68];     // As | Bs ; reused as Ts[64][65]
    float* As = sbuf;                        // [KC][68]
    float* Bs = sbuf + KC * 68;
    int tid = threadIdx.x;

    // decode linear block -> (bi, bj), bi <= bj
    int bi = 0, rem = blockIdx.x;
    while (rem >= 16 - bi) { rem -= 16 - bi; bi++; }
    int bj = bi + rem;
    int r0 = bi * 64;
    int c0 = bj * 64;

    int lrow = tid >> 5, lcol = tid & 31;
    int ty = tid >> 4, tx = tid & 15;

    float acc[4][4];
    #pragma unroll
    for (int i = 0; i < 4; i++)
        #pragma unroll
        for (int j = 0; j < 4; j++) acc[i][j] = 0.f;

    for (int kk = 0; kk < E; kk += KC) {
        #pragma unroll
        for (int it = 0; it < 8; it++) {
            int row = lrow + it * 8;
            As[lcol * 68 + row] = g_embn[(size_t)(r0 + row) * E + kk + lcol];
            Bs[lcol * 68 + row] = g_embn[(size_t)(c0 + row) * E + kk + lcol];
        }
        __syncthreads();

        #pragma unroll
        for (int k = 0; k < KC; k++) {
            float4 av = *(const float4*)&As[k * 68 + ty * 4];
            float4 bv = *(const float4*)&Bs[k * 68 + tx * 4];
            float a[4] = {av.x, av.y, av.z, av.w};
            float b[4] = {bv.x, bv.y, bv.z, bv.w};
            #pragma unroll
            for (int i = 0; i < 4; i++)
                #pragma unroll
                for (int j = 0; j < 4; j++) acc[i][j] += a[i] * b[j];
        }
        __syncthreads();
    }

    // direct tile
    #pragma unroll
    for (int i = 0; i < 4; i++)
        #pragma unroll
        for (int j = 0; j < 4; j++)
            g_sims[(size_t)(r0 + ty * 4 + i) * N + c0 + tx * 4 + j] = acc[i][j];

    // mirror tile (transposed) via smem restage
    if (bi != bj) {
        float* Ts = sbuf;   // [64][65] = 4160 floats <= 4352 available
        #pragma unroll
        for (int i = 0; i < 4; i++)
            #pragma unroll
            for (int j = 0; j < 4; j++)
                Ts[(tx * 4 + j) * 65 + ty * 4 + i] = acc[i][j];
        __syncthreads();
        #pragma unroll
        for (int i = 0; i < 4; i++)
            #pragma unroll
            for (int j = 0; j < 4; j++)
                g_sims[(size_t)(c0 + ty * 4 + i) * N + r0 + tx * 4 + j] =
                    Ts[(ty * 4 + i) * 65 + tx * 4 + j];
    }
}

// ---------------- K1b-sel: warp per row, top-32 via REDUX ------------------
__device__ __forceinline__ unsigned f2ord(float f) {
    unsigned b = __float_as_uint(f);
    return ((int)b < 0) ? ~b : (b | 0x80000000u);
}

__global__ void __launch_bounds__(256) k1b_sel() {
    int tid = threadIdx.x;
    int wid = tid >> 5, lane = tid & 31;
    int r = blockIdx.x * 8 + wid;

    const float* srow = g_sims + (size_t)r * N;
    float vals[32];
    #pragma unroll
    for (int j = 0; j < 32; j++) vals[j] = srow[j * 32 + lane];

    float bv = vals[0]; int bj = 0;
    #pragma unroll
    for (int j = 1; j < 32; j++)
        if (vals[j] > bv) { bv = vals[j]; bj = j; }

    for (int round = 0; round < TOPK; round++) {
        unsigned u  = f2ord(bv);
        unsigned mu = __reduce_max_sync(0xffffffffu, u);
        unsigned cand = (u == mu) ? (unsigned)(bj * 32 + lane) : 0x7FFFFFFFu;
        int wi = (int)__reduce_min_sync(0xffffffffu, cand);
        if (lane == 0) g_idx[r * TOPK + round] = wi;
        if (((wi & 31) == lane) && ((wi >> 5) == bj)) {
            #pragma unroll
            for (int j = 0; j < 32; j++) if (j == bj) vals[j] = -INFINITY;
            bv = vals[0]; bj = 0;
            #pragma unroll
            for (int j = 1; j < 32; j++)
                if (vals[j] > bv) { bv = vals[j]; bj = j; }
        }
        __syncwarp();
    }
}

// ---------------- K2: h = x @ W_fe via tensor cores; fused e_s/e_d ---------
#define TOK 128
#define XS_STRIDE 72
#define CS_STRIDE 136

__device__ __forceinline__ void mma16816(float* c, const unsigned* a, const unsigned* b) {
    asm volatile(
        "mma.sync.aligned.m16n8k16.row.col.f32.f16.f16.f32 "
        "{%0,%1,%2,%3}, {%4,%5,%6,%7}, {%8,%9}, {%0,%1,%2,%3};\n"
        : "+f"(c[0]), "+f"(c[1]), "+f"(c[2]), "+f"(c[3])
        : "r"(a[0]), "r"(a[1]), "r"(a[2]), "r"(a[3]), "r"(b[0]), "r"(b[1]));
}

__global__ void __launch_bounds__(512) k2_tc(const float* __restrict__ x) {
    __shared__ __align__(16) char sbuf[TOK * XS_STRIDE * 2 + E * WT_STRIDE * 2];
    __half* xs = (__half*)sbuf;
    __half* Ws = (__half*)(sbuf + TOK * XS_STRIDE * 2);
    int tid = threadIdx.x;
    int t0 = blockIdx.x * TOK;

    {
        const uint4* wsrc = (const uint4*)g_wt;
        uint4* wdst = (uint4*)Ws;
        #pragma unroll
        for (int i = 0; i < 3; i++) {
            int idx = tid + i * 512;
            if (idx < (E * WT_STRIDE * 2) / 16) wdst[idx] = wsrc[idx];
        }
        const float4* xsrc = (const float4*)(x + (size_t)t0 * F_IN);
        const float4* ws4  = (const float4*)g_ws;
        int c4 = tid & 15;
        float4 wsv = __ldg(ws4 + c4);
        float4 wdv = __ldg(ws4 + 16 + c4);
        #pragma unroll
        for (int it = 0; it < 4; it++) {
            int idx = tid + it * 512;
            int row = idx >> 4;
            float4 v = xsrc[idx];
            __half2* dst = (__half2*)(xs + row * XS_STRIDE + c4 * 4);
            dst[0] = __floats2half2_rn(v.x, v.y);
            dst[1] = __floats2half2_rn(v.z, v.w);
            float s = v.x * wsv.x + v.y * wsv.y + v.z * wsv.z + v.w * wsv.w;
            float d = v.x * wdv.x + v.y * wdv.y + v.z * wdv.z + v.w * wdv.w;
            #pragma unroll
            for (int o = 8; o; o >>= 1) {
                s += __shfl_xor_sync(0xffffffffu, s, o);
                d += __shfl_xor_sync(0xffffffffu, d, o);
            }
            if (c4 == 0) {
                int gt = t0 + row;
                int n = gt & (N - 1);
                g_es[gt] = s + __ldg(&g_eemb_s[n]);
                g_ed[gt] = d + __ldg(&g_eemb_d[n]);
            }
        }
    }
    __syncthreads();

    int lane = tid & 31, warp = tid >> 5;
    int wm = warp & 7, wn = warp >> 3;
    int gid = lane >> 2, qid = lane & 3;

    float c[8][4];
    #pragma unroll
    for (int ni = 0; ni < 8; ni++)
        #pragma unroll
        for (int q = 0; q < 4; q++) c[ni][q] = 0.f;

    #pragma unroll
    for (int kk = 0; kk < F_IN; kk += 16) {
        unsigned a[4];
        {
            int r = wm * 16 + gid;
            int cb = qid * 2 + kk;
            a[0] = *(unsigned*)(xs + r * XS_STRIDE + cb);
            a[1] = *(unsigned*)(xs + (r + 8) * XS_STRIDE + cb);
            a[2] = *(unsigned*)(xs + r * XS_STRIDE + cb + 8);
            a[3] = *(unsigned*)(xs + (r + 8) * XS_STRIDE + cb + 8);
        }
        #pragma unroll
        for (int ni = 0; ni < 8; ni++) {
            int col = wn * 64 + ni * 8 + gid;
            int rb = qid * 2 + kk;
            unsigned bb[2];
            bb[0] = *(unsigned*)(Ws + col * WT_STRIDE + rb);
            bb[1] = *(unsigned*)(Ws + col * WT_STRIDE + rb + 8);
            mma16816(c[ni], a, bb);
        }
    }
    __syncthreads();

    __half* cs = (__half*)sbuf;
    #pragma unroll
    for (int ni = 0; ni < 8; ni++) {
        int r = wm * 16 + gid;
        int e = wn * 64 + ni * 8 + qid * 2;
        *(__half2*)(cs + r * CS_STRIDE + e) =
            __floats2half2_rn(c[ni][0], c[ni][1]);
        *(__half2*)(cs + (r + 8) * CS_STRIDE + e) =
            __floats2half2_rn(c[ni][2], c[ni][3]);
    }
    __syncthreads();

    uint4* dst = (uint4*)(g_h + (size_t)t0 * E);
    #pragma unroll
    for (int it = 0; it < 4; it++) {
        int idx = tid + it * 512;
        int row = idx >> 4;
        int c8  = idx & 15;
        dst[idx] = *(uint4*)(cs + row * CS_STRIDE + c8 * 8);
    }
}

// ---------------- K3: smem-resident SpMM attention + atomic epilogue -------
__global__ void __launch_bounds__(1024) k3_spmm(const float* __restrict__ lin_W,
                                                const float* __restrict__ lin_b,
                                                float* __restrict__ y) {
    extern __shared__ __half hs[];     // [1024 rows][64 halves] = 128 KB
    int bx = blockIdx.x;
    int b  = bx >> 1;
    int h0 = (bx & 1) << 6;
    int tid = threadIdx.x;
    float halfbias = 0.5f * __ldg(lin_b);

    {
        const uint4* src = (const uint4*)(g_h + (((size_t)b) << 10) * E);
        uint4* dst = (uint4*)hs;
        int cbase = h0 >> 3;
        #pragma unroll
        for (int i = 0; i < 8; i++) {
            int idx = tid + (i << 10);
            int n = idx >> 3, c = idx & 7;
            dst[idx] = src[(n << 4) + cbase + c];
        }
    }
    __syncthreads();

    int lane = tid & 31, wid = tid >> 5;
    int g = lane >> 3, l8 = lane & 7;

    float lw[8];
    {
        const float4* lw4 = (const float4*)lin_W;
        float4 a0 = lw4[(h0 >> 2) + l8 * 2];
        float4 a1 = lw4[(h0 >> 2) + l8 * 2 + 1];
        lw[0] = a0.x; lw[1] = a0.y; lw[2] = a0.z; lw[3] = a0.w;
        lw[4] = a1.x; lw[5] = a1.y; lw[6] = a1.z; lw[7] = a1.w;
    }

    for (int pass = 0; pass < 8; pass++) {
        int n = (wid << 5) + (pass << 2) + g;
        int t = (b << 10) + n;

        float sc[4]; int ii[4];
        float es = g_es[t];
        float m = -1e30f;
        #pragma unroll
        for (int j = 0; j < 4; j++) {
            int k = l8 + (j << 3);
            int i = g_idx[(n << 5) + k];
            float v = es + g_ed[(b << 10) + i];
            v = v >= 0.f ? v : NEG_SLOPE * v;
            sc[j] = v; ii[j] = i;
            m = fmaxf(m, v);
        }
        #pragma unroll
        for (int o = 4; o; o >>= 1) m = fmaxf(m, __shfl_xor_sync(0xffffffffu, m, o));

        float s = 0.f;
        unsigned pk[4];
        #pragma unroll
        for (int j = 0; j < 4; j++) {
            float pe = __expf(sc[j] - m);
            unsigned pt = __float_as_uint(pe) & 0xFFFFFC00u;
            s += __uint_as_float(pt);
            pk[j] = pt | (unsigned)ii[j];
        }
        #pragma unroll
        for (int o = 4; o; o >>= 1) s += __shfl_xor_sync(0xffffffffu, s, o);

        float acc[8];
        #pragma unroll
        for (int q = 0; q < 8; q++) acc[q] = 0.f;
        #pragma unroll
        for (int k = 0; k < 32; k++) {
            unsigned w = __shfl_sync(0xffffffffu, pk[k >> 3], (lane & 24) + (k & 7));
            int   ridx = (int)(w & 0x3FFu);
            float a    = __uint_as_float(w & 0xFFFFFC00u);
            uint4 hv = ((const uint4*)hs)[(ridx << 3) + l8];
            const __half2* hp = (const __half2*)&hv;
            #pragma unroll
            for (int q = 0; q < 4; q++) {
                float2 f = __half22float2(hp[q]);
                acc[q * 2]     += a * f.x;
                acc[q * 2 + 1] += a * f.y;
            }
        }
        float part = 0.f;
        #pragma unroll
        for (int q = 0; q < 8; q++) part += fmaxf(acc[q], 0.f) * lw[q];
        part *= (1.f / s);
        #pragma unroll
        for (int o = 4; o; o >>= 1) part += __shfl_xor_sync(0xffffffffu, part, o);
        if (l8 == 0) atomicAdd(&y[t], part + halfbias);
    }
}

// ---------------- launch (single stream, fully serial, 5 kernels) ----------
extern "C" void kernel_launch(void* const* d_in, const int* in_sizes, int n_in,
                              void* d_out, int out_size) {
    const float* x     = (const float*)d_in[0];
    const float* emb   = (const float*)d_in[1];
    const float* Wfe   = (const float*)d_in[2];
    const float* a_src = (const float*)d_in[3];
    const float* a_dst = (const float*)d_in[4];
    const float* lin_W = (const float*)d_in[5];
    const float* lin_b = (const float*)d_in[6];
    float* y = (float*)d_out;

    static bool attr_set = false;
    if (!attr_set) {
        cudaFuncSetAttribute(k3_spmm, cudaFuncAttributeMaxDynamicSharedMemorySize,
                             131072);
        attr_set = true;
    }

    k_pre<<<N + 1 + 64, 128>>>(emb, Wfe, a_src, a_dst, y);
    k1b_sim<<<136, 256>>>();
    k1b_sel<<<N / 8, 256>>>();
    k2_tc<<<(B * N) / TOK, 512>>>(x);
    k3_spmm<<<2 * B, 1024, 131072>>>(lin_W, lin_b, y);
}

// round 17
// speedup vs baseline: 1.1343x; 1.0055x over previous
#include <cuda_runtime.h>
#include <cuda_fp16.h>
#include <math.h>

#define B 64
#define N 1024
#define F_IN 64
#define E 128
#define TOPK 32
#define NEG_SLOPE 0.2f

// ---------------- scratch (device globals; no allocation allowed) ----------
__device__ __align__(16) __half g_h[B * N * E];    // 16 MB, fp16 storage
__device__ float g_es[B * N];
__device__ float g_ed[B * N];
__device__ __align__(16) float g_embn[N * E];      // normalized emb
__device__ float g_eemb_s[N];
__device__ float g_eemb_d[N];
__device__ __align__(16) float g_ws[2 * F_IN];     // [ws_src | ws_dst]
__device__ int   g_idx[N * TOPK];
__device__ __align__(16) float g_sims[N * N];      // 4 MB cosine sims
#define WT_STRIDE 72
__device__ __align__(16) __half g_wt[E * WT_STRIDE];  // W^T fp16, padded rows

// ---------------- K_pre: fused ws + W^T + emb-normalize + y-zero -----------
__global__ void k_pre(const float* __restrict__ emb,
                      const float* __restrict__ Wfe,
                      const float* __restrict__ a_src,
                      const float* __restrict__ a_dst,
                      float* __restrict__ y) {
    int bid = blockIdx.x;
    int t = threadIdx.x;  // 128

    if (bid < N) {
        int n = bid;
        int lane = t & 31, wid = t >> 5;
        __shared__ float sm[12];
        float v  = emb[n * E + t];
        float r0 = v * v;
        float r1 = v * a_src[E + t];
        float r2 = v * a_dst[E + t];
        #pragma unroll
        for (int o = 16; o; o >>= 1) {
            r0 += __shfl_xor_sync(0xffffffffu, r0, o);
            r1 += __shfl_xor_sync(0xffffffffu, r1, o);
            r2 += __shfl_xor_sync(0xffffffffu, r2, o);
        }
        if (lane == 0) { sm[wid] = r0; sm[4 + wid] = r1; sm[8 + wid] = r2; }
        if (t < 64) y[bid * 64 + t] = 0.f;
        __syncthreads();
        float sumsq = sm[0] + sm[1] + sm[2] + sm[3];
        g_embn[n * E + t] = v * rsqrtf(sumsq);
        if (t == 0) {
            g_eemb_s[n] = sm[4] + sm[5] + sm[6] + sm[7];
            g_eemb_d[n] = sm[8] + sm[9] + sm[10] + sm[11];
        }
    } else if (bid == N) {
        if (t < F_IN) {
            float s = 0.f;
            #pragma unroll 8
            for (int e = 0; e < E; e++) s += Wfe[t * E + e] * a_src[e];
            g_ws[t] = s;
        } else {
            int f = t - F_IN;
            float s = 0.f;
            #pragma unroll 8
            for (int e = 0; e < E; e++) s += Wfe[f * E + e] * a_dst[e];
            g_ws[F_IN + f] = s;
        }
    } else {
        int idx = (bid - N - 1) * 128 + t;   // 0..8191 = e*64+f
        int e = idx >> 6, f = idx & 63;
        g_wt[e * WT_STRIDE + f] = __float2half_rn(Wfe[f * E + e]);
    }
}

// ---------------- K1b-sim: symmetric tiled GEMM (upper triangle only) ------
#define KC 32
__global__ void __launch_bounds__(256) k1b_sim() {
    __shared__ float sbuf[2 * KC * 68];     // As | Bs ; reused as Ts[64][65]
    float* As = sbuf;
    float* Bs = sbuf + KC * 68;
    int tid = threadIdx.x;

    int bi = 0, rem = blockIdx.x;
    while (rem >= 16 - bi) { rem -= 16 - bi; bi++; }
    int bj = bi + rem;
    int r0 = bi * 64;
    int c0 = bj * 64;

    int lrow = tid >> 5, lcol = tid & 31;
    int ty = tid >> 4, tx = tid & 15;

    float acc[4][4];
    #pragma unroll
    for (int i = 0; i < 4; i++)
        #pragma unroll
        for (int j = 0; j < 4; j++) acc[i][j] = 0.f;

    for (int kk = 0; kk < E; kk += KC) {
        #pragma unroll
        for (int it = 0; it < 8; it++) {
            int row = lrow + it * 8;
            As[lcol * 68 + row] = g_embn[(size_t)(r0 + row) * E + kk + lcol];
            Bs[lcol * 68 + row] = g_embn[(size_t)(c0 + row) * E + kk + lcol];
        }
        __syncthreads();

        #pragma unroll
        for (int k = 0; k < KC; k++) {
            float4 av = *(const float4*)&As[k * 68 + ty * 4];
            float4 bv = *(const float4*)&Bs[k * 68 + tx * 4];
            float a[4] = {av.x, av.y, av.z, av.w};
            float b[4] = {bv.x, bv.y, bv.z, bv.w};
            #pragma unroll
            for (int i = 0; i < 4; i++)
                #pragma unroll
                for (int j = 0; j < 4; j++) acc[i][j] += a[i] * b[j];
        }
        __syncthreads();
    }

    #pragma unroll
    for (int i = 0; i < 4; i++)
        #pragma unroll
        for (int j = 0; j < 4; j++)
            g_sims[(size_t)(r0 + ty * 4 + i) * N + c0 + tx * 4 + j] = acc[i][j];

    if (bi != bj) {
        float* Ts = sbuf;   // [64][65]
        #pragma unroll
        for (int i = 0; i < 4; i++)
            #pragma unroll
            for (int j = 0; j < 4; j++)
                Ts[(tx * 4 + j) * 65 + ty * 4 + i] = acc[i][j];
        __syncthreads();
        #pragma unroll
        for (int i = 0; i < 4; i++)
            #pragma unroll
            for (int j = 0; j < 4; j++)
                g_sims[(size_t)(c0 + ty * 4 + i) * N + r0 + tx * 4 + j] =
                    Ts[(ty * 4 + i) * 65 + tx * 4 + j];
    }
}

// ---------------- K1b-sel: warp per row, top-32 via REDUX ------------------
__device__ __forceinline__ unsigned f2ord(float f) {
    unsigned b = __float_as_uint(f);
    return ((int)b < 0) ? ~b : (b | 0x80000000u);
}

__global__ void __launch_bounds__(256) k1b_sel() {
    int tid = threadIdx.x;
    int wid = tid >> 5, lane = tid & 31;
    int r = blockIdx.x * 8 + wid;

    const float* srow = g_sims + (size_t)r * N;
    float vals[32];
    #pragma unroll
    for (int j = 0; j < 32; j++) vals[j] = srow[j * 32 + lane];

    float bv = vals[0]; int bj = 0;
    #pragma unroll
    for (int j = 1; j < 32; j++)
        if (vals[j] > bv) { bv = vals[j]; bj = j; }

    for (int round = 0; round < TOPK; round++) {
        unsigned u  = f2ord(bv);
        unsigned mu = __reduce_max_sync(0xffffffffu, u);
        unsigned cand = (u == mu) ? (unsigned)(bj * 32 + lane) : 0x7FFFFFFFu;
        int wi = (int)__reduce_min_sync(0xffffffffu, cand);
        if (lane == 0) g_idx[r * TOPK + round] = wi;
        if (((wi & 31) == lane) && ((wi >> 5) == bj)) {
            #pragma unroll
            for (int j = 0; j < 32; j++) if (j == bj) vals[j] = -INFINITY;
            bv = vals[0]; bj = 0;
            #pragma unroll
            for (int j = 1; j < 32; j++)
                if (vals[j] > bv) { bv = vals[j]; bj = j; }
        }
        __syncwarp();
    }
}

// ---------------- K2: h = x @ W_fe via tensor cores; fused e_s/e_d ---------
// 128 thr = 4 warps (2 m x 2 n); tile 32 tokens x 128 E; W via __ldg (no smem)
#define TOK 32
#define XS_STRIDE 72
#define CS_STRIDE 136

__device__ __forceinline__ void mma16816(float* c, const unsigned* a, const unsigned* b) {
    asm volatile(
        "mma.sync.aligned.m16n8k16.row.col.f32.f16.f16.f32 "
        "{%0,%1,%2,%3}, {%4,%5,%6,%7}, {%8,%9}, {%0,%1,%2,%3};\n"
        : "+f"(c[0]), "+f"(c[1]), "+f"(c[2]), "+f"(c[3])
        : "r"(a[0]), "r"(a[1]), "r"(a[2]), "r"(a[3]), "r"(b[0]), "r"(b[1]));
}

__global__ void __launch_bounds__(128) k2_tc(const float* __restrict__ x) {
    // sbuf: xs [32][72] halves (4608B) in phase 1; cs [32][136] (8704B) epilogue
    __shared__ __align__(16) char sbuf[TOK * CS_STRIDE * 2];
    __half* xs = (__half*)sbuf;
    int tid = threadIdx.x;
    int t0 = blockIdx.x * TOK;

    {
        const float4* xsrc = (const float4*)(x + (size_t)t0 * F_IN);
        const float4* ws4  = (const float4*)g_ws;
        int c4 = tid & 15;
        float4 wsv = __ldg(ws4 + c4);
        float4 wdv = __ldg(ws4 + 16 + c4);
        #pragma unroll
        for (int it = 0; it < 4; it++) {
            int idx = tid + it * 128;     // 0..511 float4
            int row = idx >> 4;
            float4 v = xsrc[idx];
            __half2* dst = (__half2*)(xs + row * XS_STRIDE + c4 * 4);
            dst[0] = __floats2half2_rn(v.x, v.y);
            dst[1] = __floats2half2_rn(v.z, v.w);
            float s = v.x * wsv.x + v.y * wsv.y + v.z * wsv.z + v.w * wsv.w;
            float d = v.x * wdv.x + v.y * wdv.y + v.z * wdv.z + v.w * wdv.w;
            #pragma unroll
            for (int o = 8; o; o >>= 1) {
                s += __shfl_xor_sync(0xffffffffu, s, o);
                d += __shfl_xor_sync(0xffffffffu, d, o);
            }
            if (c4 == 0) {
                int gt = t0 + row;
                int n = gt & (N - 1);
                g_es[gt] = s + __ldg(&g_eemb_s[n]);
                g_ed[gt] = d + __ldg(&g_eemb_d[n]);
            }
        }
    }
    __syncthreads();

    int lane = tid & 31, warp = tid >> 5;
    int wm = warp & 1, wn = warp >> 1;    // m off = wm*16, n off = wn*64
    int gid = lane >> 2, qid = lane & 3;

    float c[8][4];
    #pragma unroll
    for (int ni = 0; ni < 8; ni++)
        #pragma unroll
        for (int q = 0; q < 4; q++) c[ni][q] = 0.f;

    #pragma unroll
    for (int kk = 0; kk < F_IN; kk += 16) {
        unsigned a[4];
        {
            int r = wm * 16 + gid;
            int cb = qid * 2 + kk;
            a[0] = *(unsigned*)(xs + r * XS_STRIDE + cb);
            a[1] = *(unsigned*)(xs + (r + 8) * XS_STRIDE + cb);
            a[2] = *(unsigned*)(xs + r * XS_STRIDE + cb + 8);
            a[3] = *(unsigned*)(xs + (r + 8) * XS_STRIDE + cb + 8);
        }
        #pragma unroll
        for (int ni = 0; ni < 8; ni++) {
            int col = wn * 64 + ni * 8 + gid;
            const __half* wp = g_wt + col * WT_STRIDE + qid * 2 + kk;
            unsigned bb[2];
            bb[0] = __ldg((const unsigned*)wp);
            bb[1] = __ldg((const unsigned*)(wp + 8));
            mma16816(c[ni], a, bb);
        }
    }
    __syncthreads();   // xs no longer needed

    // epilogue: stage fp16 C tile, then coalesced uint4 stores
    __half* cs = (__half*)sbuf;   // [32][136]
    #pragma unroll
    for (int ni = 0; ni < 8; ni++) {
        int r = wm * 16 + gid;
        int e = wn * 64 + ni * 8 + qid * 2;
        *(__half2*)(cs + r * CS_STRIDE + e) =
            __floats2half2_rn(c[ni][0], c[ni][1]);
        *(__half2*)(cs + (r + 8) * CS_STRIDE + e) =
            __floats2half2_rn(c[ni][2], c[ni][3]);
    }
    __syncthreads();

    uint4* dst = (uint4*)(g_h + (size_t)t0 * E);
    #pragma unroll
    for (int it = 0; it < 4; it++) {
        int idx = tid + it * 128;   // 0..511 uint4; 16 per row
        int row = idx >> 4;
        int c8  = idx & 15;
        dst[idx] = *(uint4*)(cs + row * CS_STRIDE + c8 * 8);
    }
}

// ---------------- K3: smem-resident SpMM attention + atomic epilogue -------
__global__ void __launch_bounds__(1024) k3_spmm(const float* __restrict__ lin_W,
                                                const float* __restrict__ lin_b,
                                                float* __restrict__ y) {
    extern __shared__ __half hs[];     // [1024 rows][64 halves] = 128 KB
    int bx = blockIdx.x;
    int b  = bx >> 1;
    int h0 = (bx & 1) << 6;
    int tid = threadIdx.x;
    float halfbias = 0.5f * __ldg(lin_b);

    {
        const uint4* src = (const uint4*)(g_h + (((size_t)b) << 10) * E);
        uint4* dst = (uint4*)hs;
        int cbase = h0 >> 3;
        #pragma unroll
        for (int i = 0; i < 8; i++) {
            int idx = tid + (i << 10);
            int n = idx >> 3, c = idx & 7;
            dst[idx] = src[(n << 4) + cbase + c];
        }
    }
    __syncthreads();

    int lane = tid & 31, wid = tid >> 5;
    int g = lane >> 3, l8 = lane & 7;

    float lw[8];
    {
        const float4* lw4 = (const float4*)lin_W;
        float4 a0 = lw4[(h0 >> 2) + l8 * 2];
        float4 a1 = lw4[(h0 >> 2) + l8 * 2 + 1];
        lw[0] = a0.x; lw[1] = a0.y; lw[2] = a0.z; lw[3] = a0.w;
        lw[4] = a1.x; lw[5] = a1.y; lw[6] = a1.z; lw[7] = a1.w;
    }

    for (int pass = 0; pass < 8; pass++) {
        int n = (wid << 5) + (pass << 2) + g;
        int t = (b << 10) + n;

        float sc[4]; int ii[4];
        float es = g_es[t];
        float m = -1e30f;
        #pragma unroll
        for (int j = 0; j < 4; j++) {
            int k = l8 + (j << 3);
            int i = g_idx[(n << 5) + k];
            float v = es + g_ed[(b << 10) + i];
            v = v >= 0.f ? v : NEG_SLOPE * v;
            sc[j] = v; ii[j] = i;
            m = fmaxf(m, v);
        }
        #pragma unroll
        for (int o = 4; o; o >>= 1) m = fmaxf(m, __shfl_xor_sync(0xffffffffu, m, o));

        float s = 0.f;
        unsigned pk[4];
        #pragma unroll
        for (int j = 0; j < 4; j++) {
            float pe = __expf(sc[j] - m);
            unsigned pt = __float_as_uint(pe) & 0xFFFFFC00u;
            s += __uint_as_float(pt);
            pk[j] = pt | (unsigned)ii[j];
        }
        #pragma unroll
        for (int o = 4; o; o >>= 1) s += __shfl_xor_sync(0xffffffffu, s, o);

        float acc[8];
        #pragma unroll
        for (int q = 0; q < 8; q++) acc[q] = 0.f;
        #pragma unroll
        for (int k = 0; k < 32; k++) {
            unsigned w = __shfl_sync(0xffffffffu, pk[k >> 3], (lane & 24) + (k & 7));
            int   ridx = (int)(w & 0x3FFu);
            float a    = __uint_as_float(w & 0xFFFFFC00u);
            uint4 hv = ((const uint4*)hs)[(ridx << 3) + l8];
            const __half2* hp = (const __half2*)&hv;
            #pragma unroll
            for (int q = 0; q < 4; q++) {
                float2 f = __half22float2(hp[q]);
                acc[q * 2]     += a * f.x;
                acc[q * 2 + 1] += a * f.y;
            }
        }
        float part = 0.f;
        #pragma unroll
        for (int q = 0; q < 8; q++) part += fmaxf(acc[q], 0.f) * lw[q];
        part *= (1.f / s);
        #pragma unroll
        for (int o = 4; o; o >>= 1) part += __shfl_xor_sync(0xffffffffu, part, o);
        if (l8 == 0) atomicAdd(&y[t], part + halfbias);
    }
}

// ---------------- launch (single stream, fully serial, 5 kernels) ----------
extern "C" void kernel_launch(void* const* d_in, const int* in_sizes, int n_in,
                              void* d_out, int out_size) {
    const float* x     = (const float*)d_in[0];
    const float* emb   = (const float*)d_in[1];
    const float* Wfe   = (const float*)d_in[2];
    const float* a_src = (const float*)d_in[3];
    const float* a_dst = (const float*)d_in[4];
    const float* lin_W = (const float*)d_in[5];
    const float* lin_b = (const float*)d_in[6];
    float* y = (float*)d_out;

    static bool attr_set = false;
    if (!attr_set) {
        cudaFuncSetAttribute(k3_spmm, cudaFuncAttributeMaxDynamicSharedMemorySize,
                             131072);
        attr_set = true;
    }

    k_pre<<<N + 1 + 64, 128>>>(emb, Wfe, a_src, a_dst, y);
    k1b_sim<<<136, 256>>>();
    k1b_sel<<<N / 8, 256>>>();
    k2_tc<<<(B * N) / TOK, 128>>>(x);
    k3_spmm<<<2 * B, 1024, 131072>>>(lin_W, lin_b, y);
}